// round 15
// baseline (speedup 1.0000x reference)
#include <cuda_runtime.h>
#include <cuda_fp16.h>
#include <mma.h>
#include <math.h>
#include <cstdint>

using namespace nvcuda;

#define NMAX 100000
#define EMAX 1600000
#define CSRMAX (EMAX + NMAX)
#define BN_EPS 1e-5f
#define NEG_SLOPE 0.2f

// fp16 GEMM tiling: BM=128, BN=64, BK=32, 256 threads (8 warps @ 32x32)
#define BM 128
#define BNT 64
#define BKT 32
#define A_STRIDE 40
#define B_STRIDE 72
#define A_STAGE (BM * A_STRIDE)
#define B_STAGE (BKT * B_STRIDE)
#define GEMM_SMEM_BYTES (BM * BNT * 4)   // 32KB fp32 Csh; pipeline (29.7KB) aliases it

// ---------------- scratch (device globals; no allocs allowed) ----------------
__device__ __half g_h16[(size_t)NMAX * 256];  // buffer A (h1, z2, h3)
__device__ __half g_xh[(size_t)NMAX * 256];   // buffer B (x, x2, x3)
__device__ __half g_wh[65536];                // fp16 weights: w1@0, w2@16384, w3@49152
__device__ float  g_as[NMAX];
__device__ float  g_ad[NMAX];
__device__ float  g_as2[NMAX];
__device__ float  g_ad2[NMAX];
__device__ float  g_va[768];
__device__ int    g_rowptr[NMAX + 1];
__device__ int    g_counts[NMAX];
__device__ int    g_scan[NMAX];
__device__ int    g_cursor[NMAX];
__device__ int    g_csr[CSRMAX];
__device__ int    g_bsums[512];

// ---------------- cp.async helpers ----------------
__device__ __forceinline__ void cp_async16(void* dst, const void* src, bool pred) {
    unsigned int d = (unsigned int)__cvta_generic_to_shared(dst);
    int sz = pred ? 16 : 0;
    asm volatile("cp.async.cg.shared.global [%0],[%1],16,%2;\n" :: "r"(d), "l"(src), "r"(sz));
}
__device__ __forceinline__ void cp_commit() { asm volatile("cp.async.commit_group;\n"); }
__device__ __forceinline__ void cp_wait1() { asm volatile("cp.async.wait_group 1;\n"); }
__device__ __forceinline__ void cp_wait0() { asm volatile("cp.async.wait_group 0;\n"); }

// ---------------- small utility kernels ----------------
__global__ void k_zero2(float* a, float* b, int N) {
    int i = blockIdx.x * blockDim.x + threadIdx.x;
    if (i < N) { a[i] = 0.f; b[i] = 0.f; }
}
__global__ void k_f2h(const float* __restrict__ in, __half* __restrict__ out, int n2) {
    int i = blockIdx.x * blockDim.x + threadIdx.x;
    if (i < n2) {
        float2 v = ((const float2*)in)[i];
        ((__half2*)out)[i] = __floats2half2_rn(v.x, v.y);
    }
}
// va_s[k] = sum_n W[k,n]*as[n]; va_d likewise. One warp per k.
__global__ void k_wav(const float* __restrict__ W, const float* __restrict__ avs,
                      const float* __restrict__ avd, float* vs, float* vd, int K, int Nn) {
    int k = (blockIdx.x * blockDim.x + threadIdx.x) >> 5;
    int lane = threadIdx.x & 31;
    if (k >= K) return;
    float s = 0.f, d = 0.f;
    for (int n = lane; n < Nn; n += 32) {
        float w = W[(size_t)k * Nn + n];
        s = fmaf(w, avs[n], s);
        d = fmaf(w, avd[n], d);
    }
#pragma unroll
    for (int o = 16; o; o >>= 1) {
        s += __shfl_xor_sync(0xffffffffu, s, o);
        d += __shfl_xor_sync(0xffffffffu, d, o);
    }
    if (lane == 0) { vs[k] = s; vd[k] = d; }
}

// ---------------- CSR build ----------------
__global__ void k_initcount(int* counts, int N) {
    int i = blockIdx.x * blockDim.x + threadIdx.x;
    if (i < N) counts[i] = 1;
}
__global__ void k_count(const int* __restrict__ ei, int* counts, int E) {
    int e = blockIdx.x * blockDim.x + threadIdx.x;
    if (e < E) atomicAdd(&counts[ei[E + e]], 1);
}
__global__ void k_scan1(const int* __restrict__ counts, int* scanned, int* bsums, int N) {
    __shared__ int sh[256];
    int tid = threadIdx.x;
    int i = blockIdx.x * 256 + tid;
    int v = (i < N) ? counts[i] : 0;
    sh[tid] = v; __syncthreads();
    for (int o = 1; o < 256; o <<= 1) {
        int t = (tid >= o) ? sh[tid - o] : 0;
        __syncthreads();
        sh[tid] += t;
        __syncthreads();
    }
    if (i < N) scanned[i] = sh[tid];
    if (tid == 255) bsums[blockIdx.x] = sh[255];
}
__global__ void k_scan2(int* bsums, int NB) {
    __shared__ int sh[512];
    int tid = threadIdx.x;
    int v = (tid < NB) ? bsums[tid] : 0;
    sh[tid] = v; __syncthreads();
    for (int o = 1; o < 512; o <<= 1) {
        int t = (tid >= o) ? sh[tid - o] : 0;
        __syncthreads();
        sh[tid] += t;
        __syncthreads();
    }
    if (tid < NB) bsums[tid] = sh[tid];
}
__global__ void k_scan3(const int* __restrict__ counts, const int* __restrict__ scanned,
                        const int* __restrict__ bsums, int* row_ptr, int* cursor,
                        int* csr, int N) {
    int i = blockIdx.x * 256 + threadIdx.x;
    if (i >= N) return;
    int off = blockIdx.x ? bsums[blockIdx.x - 1] : 0;
    int incl = off + scanned[i];
    int rp = incl - counts[i];
    row_ptr[i] = rp;
    csr[rp] = i;
    cursor[i] = rp + 1;
    if (i == N - 1) row_ptr[N] = incl;
}
__global__ void k_fill(const int* __restrict__ ei, int* cursor, int* csr, int E) {
    int e = blockIdx.x * blockDim.x + threadIdx.x;
    if (e < E) {
        int d = ei[E + e];
        int s = ei[e];
        int pos = atomicAdd(&cursor[d], 1);
        csr[pos] = s;
    }
}

// ---------------- fp16 tensor-core GEMM, cp.async double-buffered ----------------
// 8 warps @ 32x32 (R13 proven shape); 3 blocks/SM via launch bounds.
// EPI 0: H = fp16(C); as_o[m] += C·avs, ad_o[m] += C·avd (atomic)
// EPI 1: v = tanh(BN(C + bias)); H = fp16(v); dots on v (atomic)
// EPI 2: H = fp16(C); no dots
template <int EPI>
__global__ __launch_bounds__(256, 3) void k_gemm_f16(
        const __half* __restrict__ A, const __half* __restrict__ B,
        __half* __restrict__ H,
        const float* __restrict__ avs, const float* __restrict__ avd,
        float* __restrict__ as_o, float* __restrict__ ad_o,
        const float* __restrict__ bias, const float* __restrict__ gam,
        const float* __restrict__ bet, const float* __restrict__ rme,
        const float* __restrict__ rva,
        int M, int K, int Nn) {
    extern __shared__ __half smemh[];
    __half* Asm = smemh;
    __half* Bsm = smemh + 2 * A_STAGE;
    float*  Csh = (float*)smemh;

    int tid  = threadIdx.x;
    int warp = tid >> 5;
    int wm   = warp >> 1;
    int wn   = warp & 1;
    int row0 = blockIdx.y * BM;
    int col0 = blockIdx.x * BNT;
    int ntiles = K / BKT;

    wmma::fragment<wmma::accumulator, 16, 16, 16, float> c[2][2];
#pragma unroll
    for (int i = 0; i < 2; i++)
#pragma unroll
        for (int j = 0; j < 2; j++) wmma::fill_fragment(c[i][j], 0.f);

    int ar = tid >> 1;
    int ac = (tid & 1) * 16;
    int br = tid >> 3;
    int bc = (tid & 7) * 8;

    auto issue = [&](int t, int s) {
        int k0 = t * BKT;
        const __half* asrc = A + (size_t)(row0 + ar) * K + k0 + ac;
        __half* adst = Asm + s * A_STAGE + ar * A_STRIDE + ac;
        bool am = (row0 + ar) < M;
        cp_async16(adst,     asrc,     am);
        cp_async16(adst + 8, asrc + 8, am);
        int nn = col0 + bc;
        const __half* bsrc = B + (size_t)(k0 + br) * Nn + nn;
        __half* bdst = Bsm + s * B_STAGE + br * B_STRIDE + bc;
        cp_async16(bdst, bsrc, nn < Nn);
    };

    issue(0, 0); cp_commit();

    for (int t = 0; t < ntiles; t++) {
        if (t + 1 < ntiles) { issue(t + 1, (t + 1) & 1); cp_commit(); cp_wait1(); }
        else                { cp_wait0(); }
        __syncthreads();
        const __half* As = Asm + (t & 1) * A_STAGE;
        const __half* Bs = Bsm + (t & 1) * B_STAGE;
#pragma unroll
        for (int kk = 0; kk < BKT; kk += 16) {
            wmma::fragment<wmma::matrix_a, 16, 16, 16, __half, wmma::row_major> a[2];
            wmma::fragment<wmma::matrix_b, 16, 16, 16, __half, wmma::row_major> b[2];
#pragma unroll
            for (int i = 0; i < 2; i++)
                wmma::load_matrix_sync(a[i], As + (wm * 32 + i * 16) * A_STRIDE + kk, A_STRIDE);
#pragma unroll
            for (int j = 0; j < 2; j++)
                wmma::load_matrix_sync(b[j], Bs + kk * B_STRIDE + wn * 32 + j * 16, B_STRIDE);
#pragma unroll
            for (int i = 0; i < 2; i++)
#pragma unroll
                for (int j = 0; j < 2; j++)
                    wmma::mma_sync(c[i][j], a[i], b[j], c[i][j]);
        }
        __syncthreads();
    }

#pragma unroll
    for (int i = 0; i < 2; i++)
#pragma unroll
        for (int j = 0; j < 2; j++)
            wmma::store_matrix_sync(Csh + (wm * 32 + i * 16) * BNT + wn * 32 + j * 16,
                                    c[i][j], BNT, wmma::mem_row_major);
    __syncthreads();

    int r  = tid >> 1;
    int n0 = (tid & 1) * 32;
    int m  = row0 + r;
    if (m >= M) return;
    float pas = 0.f, pad = 0.f;
    __half* hp = H + (size_t)m * Nn;
#pragma unroll 16
    for (int cc = 0; cc < 32; cc += 2) {
        int n = n0 + cc;
        int g = col0 + n;
        if (g >= Nn) break;   // Nn even; pairs stay valid together
        float v0 = Csh[r * BNT + n];
        float v1 = Csh[r * BNT + n + 1];
        if (EPI == 1) {
            v0 = tanhf((v0 + bias[g]     - rme[g])     * rsqrtf(rva[g]     + BN_EPS) * gam[g]     + bet[g]);
            v1 = tanhf((v1 + bias[g + 1] - rme[g + 1]) * rsqrtf(rva[g + 1] + BN_EPS) * gam[g + 1] + bet[g + 1]);
        }
        if (EPI != 2) {
            pas = fmaf(v0, avs[g], fmaf(v1, avs[g + 1], pas));
            pad = fmaf(v0, avd[g], fmaf(v1, avd[g + 1], pad));
        }
        *(__half2*)(hp + g) = __floats2half2_rn(v0, v1);
    }
    if (EPI != 2) {
        atomicAdd(&as_o[m], pas);
        atomicAdd(&ad_o[m], pad);
    }
}

__device__ __forceinline__ float leaky(float v) {
    return v > 0.f ? v : NEG_SLOPE * v;
}

// ---------------- warp-per-node softmax aggregation ----------------
// MODE 0: out fp16 = tanh(BN(acc*inv + bias)); dots with vas/vad -> as_out/ad_out (plain)
// MODE 1: out fp32 = acc*inv + bias
// MODE 2: out fp16 = acc*inv (raw, pre-GEMM)
template <int F, int MODE, typename OutT>
__global__ void k_agg(const int* __restrict__ row_ptr, const int* __restrict__ csr,
                      const __half2* __restrict__ h, const float* __restrict__ asrc,
                      const float* __restrict__ adst,
                      const float* __restrict__ bias, const float* __restrict__ gam,
                      const float* __restrict__ bet, const float* __restrict__ rme,
                      const float* __restrict__ rva,
                      const float* __restrict__ vas, const float* __restrict__ vad,
                      float* __restrict__ as_out, float* __restrict__ ad_out,
                      OutT* __restrict__ out, int N) {
    constexpr int H2  = F / 2;
    constexpr int VPL = (H2 + 31) / 32;
    int warp = (blockIdx.x * blockDim.x + threadIdx.x) >> 5;
    int lane = threadIdx.x & 31;
    if (warp >= N) return;
    int n = warp;
    int beg = row_ptr[n], end = row_ptr[n + 1];
    float adn = adst[n];

    float2 acc[VPL];
#pragma unroll
    for (int v = 0; v < VPL; v++) acc[v] = make_float2(0.f, 0.f);
    float dsum = 0.f;

    for (int base = beg; base < end; base += 32) {
        int cnt = min(32, end - base);
        float w = 0.f; int s = 0;
        if (lane < cnt) {
            s = csr[base + lane];
            w = __expf(leaky(asrc[s] + adn));
        }
        dsum += w;
        for (int j = 0; j < cnt; j++) {
            float wj = __shfl_sync(0xffffffffu, w, j);
            int   sj = __shfl_sync(0xffffffffu, s, j);
            const __half2* hp = h + (size_t)sj * H2;
#pragma unroll
            for (int v = 0; v < VPL; v++) {
                int f2 = v * 32 + lane;
                if ((H2 % 32 == 0) || f2 < H2) {
                    float2 hv = __half22float2(__ldg(hp + f2));
                    acc[v].x = fmaf(wj, hv.x, acc[v].x);
                    acc[v].y = fmaf(wj, hv.y, acc[v].y);
                }
            }
        }
    }
#pragma unroll
    for (int o = 16; o; o >>= 1) dsum += __shfl_xor_sync(0xffffffffu, dsum, o);
    float inv = 1.0f / dsum;

    float pa = 0.f, pd = 0.f;
#pragma unroll
    for (int v = 0; v < VPL; v++) {
        int f2 = v * 32 + lane;
        if ((H2 % 32) && f2 >= H2) continue;
        int f = f2 * 2;
        float v0 = acc[v].x * inv;
        float v1 = acc[v].y * inv;
        if (MODE == 0) {
            v0 = tanhf((v0 + bias[f]     - rme[f])     * rsqrtf(rva[f]     + BN_EPS) * gam[f]     + bet[f]);
            v1 = tanhf((v1 + bias[f + 1] - rme[f + 1]) * rsqrtf(rva[f + 1] + BN_EPS) * gam[f + 1] + bet[f + 1]);
            pa = fmaf(v0, vas[f], fmaf(v1, vas[f + 1], pa));
            pd = fmaf(v0, vad[f], fmaf(v1, vad[f + 1], pd));
            *(__half2*)((__half*)out + (size_t)n * F + f) = __floats2half2_rn(v0, v1);
        } else if (MODE == 2) {
            *(__half2*)((__half*)out + (size_t)n * F + f) = __floats2half2_rn(v0, v1);
        } else {
            ((float*)out)[(size_t)n * F + f]     = v0 + bias[f];
            ((float*)out)[(size_t)n * F + f + 1] = v1 + bias[f + 1];
        }
    }
    if (MODE == 0) {
#pragma unroll
        for (int o = 16; o; o >>= 1) {
            pa += __shfl_xor_sync(0xffffffffu, pa, o);
            pd += __shfl_xor_sync(0xffffffffu, pd, o);
        }
        if (lane == 0) { as_out[n] = pa; ad_out[n] = pd; }
    }
}

// ---------------- launch ----------------
extern "C" void kernel_launch(void* const* d_in, const int* in_sizes, int n_in,
                              void* d_out, int out_size) {
    const float* x  = (const float*)d_in[0];
    const int*   ei = (const int*)d_in[1];   // int32 (JAX x64 disabled)
    const float* w1  = (const float*)d_in[2];
    const float* as1 = (const float*)d_in[3];
    const float* ad1 = (const float*)d_in[4];
    const float* b1  = (const float*)d_in[5];
    const float* g1  = (const float*)d_in[6];
    const float* be1 = (const float*)d_in[7];
    const float* rm1 = (const float*)d_in[8];
    const float* rv1 = (const float*)d_in[9];
    const float* w2  = (const float*)d_in[10];
    const float* as2 = (const float*)d_in[11];
    const float* ad2 = (const float*)d_in[12];
    const float* b2  = (const float*)d_in[13];
    const float* g2  = (const float*)d_in[14];
    const float* be2 = (const float*)d_in[15];
    const float* rm2 = (const float*)d_in[16];
    const float* rv2 = (const float*)d_in[17];
    const float* w3  = (const float*)d_in[18];
    const float* as3 = (const float*)d_in[19];
    const float* ad3 = (const float*)d_in[20];
    const float* b3  = (const float*)d_in[21];
    float* out = (float*)d_out;

    int N = in_sizes[0] / 128;
    int E = in_sizes[1] / 2;

    __half *h16, *xh, *wh;
    float *as_, *ad_, *as2b, *ad2b, *va;
    int *rowptr, *counts, *scan, *cursor, *csr, *bsums;
    cudaGetSymbolAddress((void**)&h16,    g_h16);
    cudaGetSymbolAddress((void**)&xh,     g_xh);
    cudaGetSymbolAddress((void**)&wh,     g_wh);
    cudaGetSymbolAddress((void**)&as_,    g_as);
    cudaGetSymbolAddress((void**)&ad_,    g_ad);
    cudaGetSymbolAddress((void**)&as2b,   g_as2);
    cudaGetSymbolAddress((void**)&ad2b,   g_ad2);
    cudaGetSymbolAddress((void**)&va,     g_va);
    cudaGetSymbolAddress((void**)&rowptr, g_rowptr);
    cudaGetSymbolAddress((void**)&counts, g_counts);
    cudaGetSymbolAddress((void**)&scan,   g_scan);
    cudaGetSymbolAddress((void**)&cursor, g_cursor);
    cudaGetSymbolAddress((void**)&csr,    g_csr);
    cudaGetSymbolAddress((void**)&bsums,  g_bsums);

    __half* w1h = wh;
    __half* w2h = wh + 16384;
    __half* w3h = wh + 49152;
    float* va2s = va;        float* va2d = va + 128;
    float* va3s = va + 256;  float* va3d = va + 512;

    // side stream + fork/join events (created once; host-side resources only)
    static cudaStream_t s2 = nullptr;
    static cudaEvent_t evFork = nullptr, evJoin = nullptr;
    if (!s2) {
        cudaStreamCreateWithFlags(&s2, cudaStreamNonBlocking);
        cudaEventCreateWithFlags(&evFork, cudaEventDisableTiming);
        cudaEventCreateWithFlags(&evJoin, cudaEventDisableTiming);
    }

    int NB = (N + 255) / 256;
    int gemmSmem = GEMM_SMEM_BYTES;
    int rowBlocks = (N + BM - 1) / BM;
    int aggBlocks = (N + 7) / 8;

    // ---- main chain (default stream): converts + gemm1 (position 4 for ncu) ----
    k_zero2<<<NB, 256>>>(as_, ad_, N);                                          // 1
    k_f2h<<<(N * 128 / 2 + 255) / 256, 256>>>(x, xh, N * 128 / 2);              // 2
    k_f2h<<<(16384 / 2 + 255) / 256, 256>>>(w1, w1h, 16384 / 2);                // 3
    cudaEventRecord(evFork, 0);           // fork point for CSR chain
    k_gemm_f16<0><<<dim3(2, rowBlocks), 256, gemmSmem>>>                        // 4 (PROFILED)
        (xh, w1h, h16, as1, ad1, as_, ad_,
         b1, b1, b1, b1, b1, N, 128, 128);
    k_f2h<<<(32768 / 2 + 255) / 256, 256>>>(w2, w2h, 32768 / 2);
    k_f2h<<<(10240 / 2 + 255) / 256, 256>>>(w3, w3h, 10240 / 2);
    k_wav<<<(128 * 32 + 255) / 256, 256>>>(w2, as2, ad2, va2s, va2d, 128, 256);
    k_wav<<<(256 * 32 + 255) / 256, 256>>>(w3, as3, ad3, va3s, va3d, 256, 40);

    // ---- CSR chain on side stream, concurrent with gemm1/converts ----
    cudaStreamWaitEvent(s2, evFork, 0);
    k_initcount<<<NB, 256, 0, s2>>>(counts, N);
    k_count<<<(E + 255) / 256, 256, 0, s2>>>(ei, counts, E);
    k_scan1<<<NB, 256, 0, s2>>>(counts, scan, bsums, N);
    k_scan2<<<1, 512, 0, s2>>>(bsums, NB);
    k_scan3<<<NB, 256, 0, s2>>>(counts, scan, bsums, rowptr, cursor, csr, N);
    k_fill<<<(E + 255) / 256, 256, 0, s2>>>(ei, cursor, csr, E);
    cudaEventRecord(evJoin, s2);
    cudaStreamWaitEvent(0, evJoin, 0);    // join before agg1

    // ---- agg1: gather h1 -> x2 (fp16, in xh) + as2/ad2 dots ----
    k_agg<128, 0, __half><<<aggBlocks, 256>>>(rowptr, csr, (const __half2*)h16, as_, ad_,
                                              b1, g1, be1, rm1, rv1,
                                              va2s, va2d, as2b, ad2b, xh, N);

    // ---- agg2 in x-space: gather x2 -> z2 (fp16, in h16) ----
    k_agg<128, 2, __half><<<aggBlocks, 256>>>(rowptr, csr, (const __half2*)xh, as2b, ad2b,
                                              b2, b2, b2, b2, b2,
                                              va2s, va2d, as2b, ad2b, h16, N);

    // ---- gemm2: z2 @ W2, epilogue bias+BN+tanh -> x3 (xh) + as3/ad3 dots ----
    k_zero2<<<NB, 256>>>(as_, ad_, N);
    k_gemm_f16<1><<<dim3(4, rowBlocks), 256, gemmSmem>>>
        (h16, w2h, xh, va3s, va3d, as_, ad_,
         b2, g2, be2, rm2, rv2, N, 128, 256);

    // ---- gemm3: x3 @ W3 -> h3 (h16, [N,40]) ----
    k_gemm_f16<2><<<dim3(1, rowBlocks), 256, gemmSmem>>>
        (xh, w3h, h16, va3s, va3d, as_, ad_,
         b3, b3, b3, b3, b3, N, 256, 40);

    // ---- agg3: gather h3 + b3 -> out (fp32) ----
    k_agg<40, 1, float><<<aggBlocks, 256>>>(rowptr, csr, (const __half2*)h16, as_, ad_,
                                            b3, b3, b3, b3, b3,
                                            va3s, va3d, as2b, ad2b, out, N);
}

// round 16
// speedup vs baseline: 1.4284x; 1.4284x over previous
#include <cuda_runtime.h>
#include <cuda_fp16.h>
#include <mma.h>
#include <math.h>
#include <cstdint>

using namespace nvcuda;

#define NMAX 100000
#define EMAX 1600000
#define CSRMAX (EMAX + NMAX)
#define BN_EPS 1e-5f
#define NEG_SLOPE 0.2f

// fp16 GEMM tiling: BM=128, BN=64, BK=32, 256 threads (8 warps @ 32x32), 3-stage pipe
#define BM 128
#define BNT 64
#define BKT 32
#define A_STRIDE 40
#define B_STRIDE 72
#define A_STAGE (BM * A_STRIDE)
#define B_STAGE (BKT * B_STRIDE)
#define NSTAGE 3
#define PIPE_BYTES (NSTAGE * (A_STAGE + B_STAGE) * 2)   // 44544 B
#define GEMM_SMEM_BYTES PIPE_BYTES                      // Csh (32KB) aliases within

// ---------------- scratch (device globals; no allocs allowed) ----------------
__device__ __half g_h16[(size_t)NMAX * 256];  // buffer A (h1, z2, h3)
__device__ __half g_xh[(size_t)NMAX * 256];   // buffer B (x, x2, x3)
__device__ __half g_wh[65536];                // fp16 weights: w1@0, w2@16384, w3@49152
__device__ float  g_as[NMAX];
__device__ float  g_ad[NMAX];
__device__ float  g_as2[NMAX];
__device__ float  g_ad2[NMAX];
__device__ float  g_va[768];
__device__ int    g_rowptr[NMAX + 1];
__device__ int    g_counts[NMAX];
__device__ int    g_scan[NMAX];
__device__ int    g_cursor[NMAX];
__device__ int    g_csr[CSRMAX];
__device__ int    g_bsums[512];

// ---------------- cp.async helpers ----------------
__device__ __forceinline__ void cp_async16(void* dst, const void* src, bool pred) {
    unsigned int d = (unsigned int)__cvta_generic_to_shared(dst);
    int sz = pred ? 16 : 0;
    asm volatile("cp.async.cg.shared.global [%0],[%1],16,%2;\n" :: "r"(d), "l"(src), "r"(sz));
}
__device__ __forceinline__ void cp_commit() { asm volatile("cp.async.commit_group;\n"); }
__device__ __forceinline__ void cp_wait2() { asm volatile("cp.async.wait_group 2;\n"); }
__device__ __forceinline__ void cp_wait1() { asm volatile("cp.async.wait_group 1;\n"); }
__device__ __forceinline__ void cp_wait0() { asm volatile("cp.async.wait_group 0;\n"); }

// ---------------- small utility kernels ----------------
__global__ void k_zero2(float* a, float* b, int N) {
    int i = blockIdx.x * blockDim.x + threadIdx.x;
    if (i < N) { a[i] = 0.f; b[i] = 0.f; }
}
__global__ void k_f2h(const float* __restrict__ in, __half* __restrict__ out, int n2) {
    int i = blockIdx.x * blockDim.x + threadIdx.x;
    if (i < n2) {
        float2 v = ((const float2*)in)[i];
        ((__half2*)out)[i] = __floats2half2_rn(v.x, v.y);
    }
}
// va_s[k] = sum_n W[k,n]*as[n]; va_d likewise. One warp per k.
__global__ void k_wav(const float* __restrict__ W, const float* __restrict__ avs,
                      const float* __restrict__ avd, float* vs, float* vd, int K, int Nn) {
    int k = (blockIdx.x * blockDim.x + threadIdx.x) >> 5;
    int lane = threadIdx.x & 31;
    if (k >= K) return;
    float s = 0.f, d = 0.f;
    for (int n = lane; n < Nn; n += 32) {
        float w = W[(size_t)k * Nn + n];
        s = fmaf(w, avs[n], s);
        d = fmaf(w, avd[n], d);
    }
#pragma unroll
    for (int o = 16; o; o >>= 1) {
        s += __shfl_xor_sync(0xffffffffu, s, o);
        d += __shfl_xor_sync(0xffffffffu, d, o);
    }
    if (lane == 0) { vs[k] = s; vd[k] = d; }
}

// ---------------- CSR build ----------------
__global__ void k_initcount(int* counts, int N) {
    int i = blockIdx.x * blockDim.x + threadIdx.x;
    if (i < N) counts[i] = 1;
}
__global__ void k_count(const int* __restrict__ ei, int* counts, int E) {
    int e = blockIdx.x * blockDim.x + threadIdx.x;
    if (e < E) atomicAdd(&counts[ei[E + e]], 1);
}
__global__ void k_scan1(const int* __restrict__ counts, int* scanned, int* bsums, int N) {
    __shared__ int sh[256];
    int tid = threadIdx.x;
    int i = blockIdx.x * 256 + tid;
    int v = (i < N) ? counts[i] : 0;
    sh[tid] = v; __syncthreads();
    for (int o = 1; o < 256; o <<= 1) {
        int t = (tid >= o) ? sh[tid - o] : 0;
        __syncthreads();
        sh[tid] += t;
        __syncthreads();
    }
    if (i < N) scanned[i] = sh[tid];
    if (tid == 255) bsums[blockIdx.x] = sh[255];
}
__global__ void k_scan2(int* bsums, int NB) {
    __shared__ int sh[512];
    int tid = threadIdx.x;
    int v = (tid < NB) ? bsums[tid] : 0;
    sh[tid] = v; __syncthreads();
    for (int o = 1; o < 512; o <<= 1) {
        int t = (tid >= o) ? sh[tid - o] : 0;
        __syncthreads();
        sh[tid] += t;
        __syncthreads();
    }
    if (tid < NB) bsums[tid] = sh[tid];
}
__global__ void k_scan3(const int* __restrict__ counts, const int* __restrict__ scanned,
                        const int* __restrict__ bsums, int* row_ptr, int* cursor,
                        int* csr, int N) {
    int i = blockIdx.x * 256 + threadIdx.x;
    if (i >= N) return;
    int off = blockIdx.x ? bsums[blockIdx.x - 1] : 0;
    int incl = off + scanned[i];
    int rp = incl - counts[i];
    row_ptr[i] = rp;
    csr[rp] = i;
    cursor[i] = rp + 1;
    if (i == N - 1) row_ptr[N] = incl;
}
__global__ void k_fill(const int* __restrict__ ei, int* cursor, int* csr, int E) {
    int e = blockIdx.x * blockDim.x + threadIdx.x;
    if (e < E) {
        int d = ei[E + e];
        int s = ei[e];
        int pos = atomicAdd(&cursor[d], 1);
        csr[pos] = s;
    }
}

// ---------------- fp16 tensor-core GEMM, 3-stage cp.async pipeline ----------------
// 8 warps @ 32x32 (R13 proven shape), 2 blocks/SM.
// EPI 0: H = fp16(C); as_o[m] += C·avs, ad_o[m] += C·avd (atomic)
// EPI 1: v = tanh(BN(C + bias)); H = fp16(v); dots on v (atomic)
// EPI 2: H = fp16(C); no dots
template <int EPI>
__global__ __launch_bounds__(256, 2) void k_gemm_f16(
        const __half* __restrict__ A, const __half* __restrict__ B,
        __half* __restrict__ H,
        const float* __restrict__ avs, const float* __restrict__ avd,
        float* __restrict__ as_o, float* __restrict__ ad_o,
        const float* __restrict__ bias, const float* __restrict__ gam,
        const float* __restrict__ bet, const float* __restrict__ rme,
        const float* __restrict__ rva,
        int M, int K, int Nn) {
    extern __shared__ __half smemh[];
    __half* Asm = smemh;                            // NSTAGE stages of 128x40
    __half* Bsm = smemh + NSTAGE * A_STAGE;         // NSTAGE stages of 32x72
    float*  Csh = (float*)smemh;                    // alias, used after mainloop

    int tid  = threadIdx.x;
    int warp = tid >> 5;
    int wm   = warp >> 1;
    int wn   = warp & 1;
    int row0 = blockIdx.y * BM;
    int col0 = blockIdx.x * BNT;
    int ntiles = K / BKT;

    wmma::fragment<wmma::accumulator, 16, 16, 16, float> c[2][2];
#pragma unroll
    for (int i = 0; i < 2; i++)
#pragma unroll
        for (int j = 0; j < 2; j++) wmma::fill_fragment(c[i][j], 0.f);

    int ar = tid >> 1;
    int ac = (tid & 1) * 16;
    int br = tid >> 3;
    int bc = (tid & 7) * 8;

    auto issue = [&](int t) {
        int s = t % NSTAGE;
        int k0 = t * BKT;
        const __half* asrc = A + (size_t)(row0 + ar) * K + k0 + ac;
        __half* adst = Asm + s * A_STAGE + ar * A_STRIDE + ac;
        bool am = (row0 + ar) < M;
        cp_async16(adst,     asrc,     am);
        cp_async16(adst + 8, asrc + 8, am);
        int nn = col0 + bc;
        const __half* bsrc = B + (size_t)(k0 + br) * Nn + nn;
        __half* bdst = Bsm + s * B_STAGE + br * B_STRIDE + bc;
        cp_async16(bdst, bsrc, nn < Nn);
        cp_commit();
    };

    issue(0);
    if (ntiles > 1) issue(1);

    for (int t = 0; t < ntiles; t++) {
        if (t + 2 < ntiles)      { issue(t + 2); cp_wait2(); }
        else if (t + 1 < ntiles) { cp_wait1(); }
        else                     { cp_wait0(); }
        __syncthreads();
        const __half* As = Asm + (t % NSTAGE) * A_STAGE;
        const __half* Bs = Bsm + (t % NSTAGE) * B_STAGE;
#pragma unroll
        for (int kk = 0; kk < BKT; kk += 16) {
            wmma::fragment<wmma::matrix_a, 16, 16, 16, __half, wmma::row_major> a[2];
            wmma::fragment<wmma::matrix_b, 16, 16, 16, __half, wmma::row_major> b[2];
#pragma unroll
            for (int i = 0; i < 2; i++)
                wmma::load_matrix_sync(a[i], As + (wm * 32 + i * 16) * A_STRIDE + kk, A_STRIDE);
#pragma unroll
            for (int j = 0; j < 2; j++)
                wmma::load_matrix_sync(b[j], Bs + kk * B_STRIDE + wn * 32 + j * 16, B_STRIDE);
#pragma unroll
            for (int i = 0; i < 2; i++)
#pragma unroll
                for (int j = 0; j < 2; j++)
                    wmma::mma_sync(c[i][j], a[i], b[j], c[i][j]);
        }
        __syncthreads();
    }

#pragma unroll
    for (int i = 0; i < 2; i++)
#pragma unroll
        for (int j = 0; j < 2; j++)
            wmma::store_matrix_sync(Csh + (wm * 32 + i * 16) * BNT + wn * 32 + j * 16,
                                    c[i][j], BNT, wmma::mem_row_major);
    __syncthreads();

    int r  = tid >> 1;
    int n0 = (tid & 1) * 32;
    int m  = row0 + r;
    if (m >= M) return;
    float pas = 0.f, pad = 0.f;
    __half* hp = H + (size_t)m * Nn;
#pragma unroll 16
    for (int cc = 0; cc < 32; cc += 2) {
        int n = n0 + cc;
        int g = col0 + n;
        if (g >= Nn) break;   // Nn even; pairs stay valid together
        float v0 = Csh[r * BNT + n];
        float v1 = Csh[r * BNT + n + 1];
        if (EPI == 1) {
            v0 = tanhf((v0 + bias[g]     - rme[g])     * rsqrtf(rva[g]     + BN_EPS) * gam[g]     + bet[g]);
            v1 = tanhf((v1 + bias[g + 1] - rme[g + 1]) * rsqrtf(rva[g + 1] + BN_EPS) * gam[g + 1] + bet[g + 1]);
        }
        if (EPI != 2) {
            pas = fmaf(v0, avs[g], fmaf(v1, avs[g + 1], pas));
            pad = fmaf(v0, avd[g], fmaf(v1, avd[g + 1], pad));
        }
        *(__half2*)(hp + g) = __floats2half2_rn(v0, v1);
    }
    if (EPI != 2) {
        atomicAdd(&as_o[m], pas);
        atomicAdd(&ad_o[m], pad);
    }
}

__device__ __forceinline__ float leaky(float v) {
    return v > 0.f ? v : NEG_SLOPE * v;
}

// ---------------- warp-per-node softmax aggregation ----------------
// MODE 0: out fp16 = tanh(BN(acc*inv + bias)); dots with vas/vad -> as_out/ad_out (plain)
// MODE 1: out fp32 = acc*inv + bias
// MODE 2: out fp16 = acc*inv (raw, pre-GEMM)
template <int F, int MODE, typename OutT>
__global__ void k_agg(const int* __restrict__ row_ptr, const int* __restrict__ csr,
                      const __half2* __restrict__ h, const float* __restrict__ asrc,
                      const float* __restrict__ adst,
                      const float* __restrict__ bias, const float* __restrict__ gam,
                      const float* __restrict__ bet, const float* __restrict__ rme,
                      const float* __restrict__ rva,
                      const float* __restrict__ vas, const float* __restrict__ vad,
                      float* __restrict__ as_out, float* __restrict__ ad_out,
                      OutT* __restrict__ out, int N) {
    constexpr int H2  = F / 2;
    constexpr int VPL = (H2 + 31) / 32;
    int warp = (blockIdx.x * blockDim.x + threadIdx.x) >> 5;
    int lane = threadIdx.x & 31;
    if (warp >= N) return;
    int n = warp;
    int beg = row_ptr[n], end = row_ptr[n + 1];
    float adn = adst[n];

    float2 acc[VPL];
#pragma unroll
    for (int v = 0; v < VPL; v++) acc[v] = make_float2(0.f, 0.f);
    float dsum = 0.f;

    for (int base = beg; base < end; base += 32) {
        int cnt = min(32, end - base);
        float w = 0.f; int s = 0;
        if (lane < cnt) {
            s = csr[base + lane];
            w = __expf(leaky(asrc[s] + adn));
        }
        dsum += w;
        for (int j = 0; j < cnt; j++) {
            float wj = __shfl_sync(0xffffffffu, w, j);
            int   sj = __shfl_sync(0xffffffffu, s, j);
            const __half2* hp = h + (size_t)sj * H2;
#pragma unroll
            for (int v = 0; v < VPL; v++) {
                int f2 = v * 32 + lane;
                if ((H2 % 32 == 0) || f2 < H2) {
                    float2 hv = __half22float2(__ldg(hp + f2));
                    acc[v].x = fmaf(wj, hv.x, acc[v].x);
                    acc[v].y = fmaf(wj, hv.y, acc[v].y);
                }
            }
        }
    }
#pragma unroll
    for (int o = 16; o; o >>= 1) dsum += __shfl_xor_sync(0xffffffffu, dsum, o);
    float inv = 1.0f / dsum;

    float pa = 0.f, pd = 0.f;
#pragma unroll
    for (int v = 0; v < VPL; v++) {
        int f2 = v * 32 + lane;
        if ((H2 % 32) && f2 >= H2) continue;
        int f = f2 * 2;
        float v0 = acc[v].x * inv;
        float v1 = acc[v].y * inv;
        if (MODE == 0) {
            v0 = tanhf((v0 + bias[f]     - rme[f])     * rsqrtf(rva[f]     + BN_EPS) * gam[f]     + bet[f]);
            v1 = tanhf((v1 + bias[f + 1] - rme[f + 1]) * rsqrtf(rva[f + 1] + BN_EPS) * gam[f + 1] + bet[f + 1]);
            pa = fmaf(v0, vas[f], fmaf(v1, vas[f + 1], pa));
            pd = fmaf(v0, vad[f], fmaf(v1, vad[f + 1], pd));
            *(__half2*)((__half*)out + (size_t)n * F + f) = __floats2half2_rn(v0, v1);
        } else if (MODE == 2) {
            *(__half2*)((__half*)out + (size_t)n * F + f) = __floats2half2_rn(v0, v1);
        } else {
            ((float*)out)[(size_t)n * F + f]     = v0 + bias[f];
            ((float*)out)[(size_t)n * F + f + 1] = v1 + bias[f + 1];
        }
    }
    if (MODE == 0) {
#pragma unroll
        for (int o = 16; o; o >>= 1) {
            pa += __shfl_xor_sync(0xffffffffu, pa, o);
            pd += __shfl_xor_sync(0xffffffffu, pd, o);
        }
        if (lane == 0) { as_out[n] = pa; ad_out[n] = pd; }
    }
}

// ---------------- launch ----------------
extern "C" void kernel_launch(void* const* d_in, const int* in_sizes, int n_in,
                              void* d_out, int out_size) {
    const float* x  = (const float*)d_in[0];
    const int*   ei = (const int*)d_in[1];   // int32 (JAX x64 disabled)
    const float* w1  = (const float*)d_in[2];
    const float* as1 = (const float*)d_in[3];
    const float* ad1 = (const float*)d_in[4];
    const float* b1  = (const float*)d_in[5];
    const float* g1  = (const float*)d_in[6];
    const float* be1 = (const float*)d_in[7];
    const float* rm1 = (const float*)d_in[8];
    const float* rv1 = (const float*)d_in[9];
    const float* w2  = (const float*)d_in[10];
    const float* as2 = (const float*)d_in[11];
    const float* ad2 = (const float*)d_in[12];
    const float* b2  = (const float*)d_in[13];
    const float* g2  = (const float*)d_in[14];
    const float* be2 = (const float*)d_in[15];
    const float* rm2 = (const float*)d_in[16];
    const float* rv2 = (const float*)d_in[17];
    const float* w3  = (const float*)d_in[18];
    const float* as3 = (const float*)d_in[19];
    const float* ad3 = (const float*)d_in[20];
    const float* b3  = (const float*)d_in[21];
    float* out = (float*)d_out;

    int N = in_sizes[0] / 128;
    int E = in_sizes[1] / 2;

    __half *h16, *xh, *wh;
    float *as_, *ad_, *as2b, *ad2b, *va;
    int *rowptr, *counts, *scan, *cursor, *csr, *bsums;
    cudaGetSymbolAddress((void**)&h16,    g_h16);
    cudaGetSymbolAddress((void**)&xh,     g_xh);
    cudaGetSymbolAddress((void**)&wh,     g_wh);
    cudaGetSymbolAddress((void**)&as_,    g_as);
    cudaGetSymbolAddress((void**)&ad_,    g_ad);
    cudaGetSymbolAddress((void**)&as2b,   g_as2);
    cudaGetSymbolAddress((void**)&ad2b,   g_ad2);
    cudaGetSymbolAddress((void**)&va,     g_va);
    cudaGetSymbolAddress((void**)&rowptr, g_rowptr);
    cudaGetSymbolAddress((void**)&counts, g_counts);
    cudaGetSymbolAddress((void**)&scan,   g_scan);
    cudaGetSymbolAddress((void**)&cursor, g_cursor);
    cudaGetSymbolAddress((void**)&csr,    g_csr);
    cudaGetSymbolAddress((void**)&bsums,  g_bsums);

    __half* w1h = wh;
    __half* w2h = wh + 16384;
    __half* w3h = wh + 49152;
    float* va2s = va;        float* va2d = va + 128;
    float* va3s = va + 256;  float* va3d = va + 512;

    static bool attr = false;
    if (!attr) {
        cudaFuncSetAttribute(k_gemm_f16<0>, cudaFuncAttributeMaxDynamicSharedMemorySize, GEMM_SMEM_BYTES);
        cudaFuncSetAttribute(k_gemm_f16<1>, cudaFuncAttributeMaxDynamicSharedMemorySize, GEMM_SMEM_BYTES);
        cudaFuncSetAttribute(k_gemm_f16<2>, cudaFuncAttributeMaxDynamicSharedMemorySize, GEMM_SMEM_BYTES);
        attr = true;
    }

    int NB = (N + 255) / 256;
    int gemmSmem = GEMM_SMEM_BYTES;
    int rowBlocks = (N + BM - 1) / BM;
    int aggBlocks = (N + 7) / 8;

    // ---- layer 1 GEMM at launch position 4 (ncu sampling) ----
    k_zero2<<<NB, 256>>>(as_, ad_, N);                                          // 1
    k_f2h<<<(N * 128 / 2 + 255) / 256, 256>>>(x, xh, N * 128 / 2);              // 2
    k_f2h<<<(16384 / 2 + 255) / 256, 256>>>(w1, w1h, 16384 / 2);                // 3
    k_gemm_f16<0><<<dim3(2, rowBlocks), 256, gemmSmem>>>                        // 4 (PROFILED)
        (xh, w1h, h16, as1, ad1, as_, ad_,
         b1, b1, b1, b1, b1, N, 128, 128);
    k_f2h<<<(32768 / 2 + 255) / 256, 256>>>(w2, w2h, 32768 / 2);                // 5
    k_f2h<<<(10240 / 2 + 255) / 256, 256>>>(w3, w3h, 10240 / 2);                // 6
    k_wav<<<(128 * 32 + 255) / 256, 256>>>(w2, as2, ad2, va2s, va2d, 128, 256); // 7
    k_wav<<<(256 * 32 + 255) / 256, 256>>>(w3, as3, ad3, va3s, va3d, 256, 40);  // 8
    k_initcount<<<NB, 256>>>(counts, N);                                        // 9
    k_count<<<(E + 255) / 256, 256>>>(ei, counts, E);                           // 10
    k_scan1<<<NB, 256>>>(counts, scan, bsums, N);                               // 11
    k_scan2<<<1, 512>>>(bsums, NB);                                             // 12
    k_scan3<<<NB, 256>>>(counts, scan, bsums, rowptr, cursor, csr, N);          // 13
    k_fill<<<(E + 255) / 256, 256>>>(ei, cursor, csr, E);                       // 14

    // ---- agg1: gather h1 -> x2 (fp16, in xh) + as2/ad2 dots ----
    k_agg<128, 0, __half><<<aggBlocks, 256>>>(rowptr, csr, (const __half2*)h16, as_, ad_,
                                              b1, g1, be1, rm1, rv1,
                                              va2s, va2d, as2b, ad2b, xh, N);

    // ---- agg2 in x-space: gather x2 -> z2 (fp16, in h16) ----
    k_agg<128, 2, __half><<<aggBlocks, 256>>>(rowptr, csr, (const __half2*)xh, as2b, ad2b,
                                              b2, b2, b2, b2, b2,
                                              va2s, va2d, as2b, ad2b, h16, N);

    // ---- gemm2: z2 @ W2, epilogue bias+BN+tanh -> x3 (xh) + as3/ad3 dots ----
    k_zero2<<<NB, 256>>>(as_, ad_, N);
    k_gemm_f16<1><<<dim3(4, rowBlocks), 256, gemmSmem>>>
        (h16, w2h, xh, va3s, va3d, as_, ad_,
         b2, g2, be2, rm2, rv2, N, 128, 256);

    // ---- gemm3: x3 @ W3 -> h3 (h16, [N,40]) ----
    k_gemm_f16<2><<<dim3(1, rowBlocks), 256, gemmSmem>>>
        (xh, w3h, h16, va3s, va3d, as_, ad_,
         b3, b3, b3, b3, b3, N, 256, 40);

    // ---- agg3: gather h3 + b3 -> out (fp32) ----
    k_agg<40, 1, float><<<aggBlocks, 256>>>(rowptr, csr, (const __half2*)h16, as_, ad_,
                                            b3, b3, b3, b3, b3,
                                            va3s, va3d, as2b, ad2b, out, N);
}